// round 6
// baseline (speedup 1.0000x reference)
#include <cuda_runtime.h>
#include <cstdint>

#define T     2048
#define E     512
#define HD    512
#define G4    2048   /* 4*HD */
#define TAGS  32
#define START 30
#define STOP  31
#define NEGV  (-10000.0f)

#define CANARY 0xFFFFFFFFu

// ---------------- scratch (device globals; no allocation) ----------------
__device__ float g_x[T * E];          // gathered embeddings          4 MB
__device__ float g_xg[2][T * G4];     // precomputed input gates     32 MB
__device__ float g_h[2][T * HD];      // LSTM hidden outputs          8 MB
__device__ float g_feats[T * TAGS];   // emissions                  256 KB

// ---------------- gather + poison fused ----------------
__global__ void k_prep(const int* __restrict__ sent, const float* __restrict__ emb) {
    int blk = blockIdx.x;
    if (blk < T) {
        const float4* src = (const float4*)(emb + (size_t)sent[blk] * E);
        ((float4*)(g_x + (size_t)blk * E))[threadIdx.x] = src[threadIdx.x];
    } else {
        int cb = blk - T;
        unsigned* dst = (unsigned*)g_h + (size_t)cb * 1024 + threadIdx.x * 8;
        uint4 v = {CANARY, CANARY, CANARY, CANARY};
        *(uint4*)(dst)     = v;
        *(uint4*)(dst + 4) = v;
    }
}

// ---------------- packed f32x2 helpers ----------------
#define FMA2(acc, a, b) asm("fma.rn.f32x2 %0, %1, %2, %0;" : "+l"(acc) : "l"(a), "l"(b))
#define ADD2(acc, b)    asm("add.rn.f32x2 %0, %0, %1;" : "+l"(acc) : "l"(b))
#define PACK2(out, lo, hi) asm("mov.b64 %0, {%1, %2};" : "=l"(out) : "f"(lo), "f"(hi))

// ---------------- input GEMM: g_xg[d] = g_x @ W_ih[d]^T + b[d] (FFMA2) -------
#define BM 128
#define BN 128
#define BK 16
__global__ void __launch_bounds__(256) k_gemm(const float* __restrict__ w_ih_f,
                                              const float* __restrict__ b_f,
                                              const float* __restrict__ w_ih_b,
                                              const float* __restrict__ b_b) {
    int d = blockIdx.z;
    const float* W    = d ? w_ih_b : w_ih_f;
    const float* bias = d ? b_b    : b_f;

    __shared__ float As[BK][BM];
    __shared__ float Bs[BK][BN];

    int tid = threadIdx.x;
    int tx = tid & 15, ty = tid >> 4;
    int t0 = blockIdx.y * BM, r0 = blockIdx.x * BN;

    unsigned long long acc2[8][4];
#pragma unroll
    for (int i = 0; i < 8; i++)
#pragma unroll
        for (int j = 0; j < 4; j++) acc2[i][j] = 0ull;

    int lm = tid >> 2;            // 0..63
    int lk = (tid & 3) * 4;       // 0,4,8,12

    for (int k0 = 0; k0 < E; k0 += BK) {
#pragma unroll
        for (int rep = 0; rep < 2; rep++) {
            float4 v = *(const float4*)(g_x + (size_t)(t0 + lm + rep * 64) * E + k0 + lk);
            As[lk + 0][lm + rep * 64] = v.x;
            As[lk + 1][lm + rep * 64] = v.y;
            As[lk + 2][lm + rep * 64] = v.z;
            As[lk + 3][lm + rep * 64] = v.w;
            float4 w = *(const float4*)(W + (size_t)(r0 + lm + rep * 64) * E + k0 + lk);
            Bs[lk + 0][lm + rep * 64] = w.x;
            Bs[lk + 1][lm + rep * 64] = w.y;
            Bs[lk + 2][lm + rep * 64] = w.z;
            Bs[lk + 3][lm + rep * 64] = w.w;
        }
        __syncthreads();
#pragma unroll
        for (int k = 0; k < BK; k++) {
            float a[8];
            *(float4*)(a)     = *(const float4*)&As[k][ty * 8];
            *(float4*)(a + 4) = *(const float4*)&As[k][ty * 8 + 4];
            ulonglong2 bl = *(const ulonglong2*)&Bs[k][tx * 8];
            ulonglong2 bh = *(const ulonglong2*)&Bs[k][tx * 8 + 4];
            unsigned long long bq[4] = {bl.x, bl.y, bh.x, bh.y};
#pragma unroll
            for (int i = 0; i < 8; i++) {
                unsigned long long ad;
                PACK2(ad, a[i], a[i]);
                FMA2(acc2[i][0], ad, bq[0]);
                FMA2(acc2[i][1], ad, bq[1]);
                FMA2(acc2[i][2], ad, bq[2]);
                FMA2(acc2[i][3], ad, bq[3]);
            }
        }
        __syncthreads();
    }

    float* out = g_xg[d];
#pragma unroll
    for (int i = 0; i < 8; i++) {
        int t = t0 + ty * 8 + i;
#pragma unroll
        for (int jp = 0; jp < 4; jp += 2) {
            int r = r0 + tx * 8 + jp * 2;
            float4 v;
            v.x = __uint_as_float((unsigned)(acc2[i][jp]     & 0xFFFFFFFFull)) + bias[r + 0];
            v.y = __uint_as_float((unsigned)(acc2[i][jp]     >> 32))           + bias[r + 1];
            v.z = __uint_as_float((unsigned)(acc2[i][jp + 1] & 0xFFFFFFFFull)) + bias[r + 2];
            v.w = __uint_as_float((unsigned)(acc2[i][jp + 1] >> 32))           + bias[r + 3];
            *(float4*)(out + (size_t)t * G4 + r) = v;
        }
    }
}

// ---------------- persistent bidirectional LSTM recurrence ----------------
// 128 CTAs x 256 threads. CTA (d*64+b) owns h[8b,8b+8) of direction d; warp w
// owns row 8b+w end-to-end. Per step: cooperative poll (each thread 2 floats,
// v2 volatile), STS to parity double-buffered smem, ONE __syncthreads, per-warp
// full 512-dot (lane = gate*8+seg, W_hh in registers), shfl-xor reduce within
// 8-lane groups, gate gather via idx-shfl, activations replicated (fast
// __fdividef), lane0 publishes h (data-as-flag into canary-poisoned g_h).
__device__ __forceinline__ float sig_f(float x) {
    return __fdividef(1.f, 1.f + __expf(-x));
}
__device__ __forceinline__ float tanh_f(float x) {
    return 1.f - __fdividef(2.f, __expf(2.f * x) + 1.f);
}

__global__ void __launch_bounds__(256, 1) k_lstm(const float* __restrict__ w_hh_f,
                                                 const float* __restrict__ w_hh_b,
                                                 const float* __restrict__ h0,
                                                 const float* __restrict__ c0) {
    int cta = blockIdx.x;
    int d = cta >> 6;
    int b = cta & 63;
    const float* Whh = d ? w_hh_b : w_hh_f;

    int tid  = threadIdx.x;
    int w    = tid >> 5;            // warp = local h-row
    int lane = tid & 31;
    int gate = lane >> 3, seg = lane & 7;
    int row  = b * 8 + w;
    int grow = gate * HD + row;

    // weights: 64 cols (seg*64 ..) of row grow, packed as f32 pairs
    unsigned long long wq[32];
    {
        const ulonglong2* wr = (const ulonglong2*)(Whh + (size_t)grow * HD + seg * 64);
#pragma unroll
        for (int m = 0; m < 16; m++) {
            ulonglong2 v = wr[m];
            wq[2 * m] = v.x; wq[2 * m + 1] = v.y;
        }
    }

    __shared__ float sh_h[2][HD];   // parity double buffer

    const float* xg = g_xg[d];
    float* hout = g_h[d];

    float c = __ldg(c0 + d * HD + row);   // replicated across lanes

    // xg prefetch: lanes with seg==0 hold xg for their gate
    int t0i = d ? (T - 1) : 0;
    float xg_cur = 0.f;
    if (seg == 0) xg_cur = __ldg(xg + (size_t)t0i * G4 + grow);

    for (int s = 0; s < T; s++) {
        int t = d ? (T - 1 - s) : s;
        int buf = s & 1;

        // cooperative poll: this thread's 2 floats of h_prev
        float2 hv;
        if (s == 0) {
            hv = *(const float2*)(h0 + d * HD + tid * 2);
        } else {
            int tp = d ? (t + 1) : (t - 1);
            const float* hp = hout + (size_t)tp * HD + tid * 2;
            unsigned a, bb;
            do {
                asm volatile("ld.volatile.global.v2.u32 {%0, %1}, [%2];"
                             : "=r"(a), "=r"(bb) : "l"(hp));
            } while (a == CANARY || bb == CANARY);
            hv.x = __uint_as_float(a);
            hv.y = __uint_as_float(bb);
        }
        sh_h[buf][tid * 2]     = hv.x;
        sh_h[buf][tid * 2 + 1] = hv.y;
        __syncthreads();

        // per-warp dot: lane covers cols [seg*64, seg*64+64) of gate row
        const ulonglong2* hq = (const ulonglong2*)(sh_h[buf] + seg * 64);
        unsigned long long a0 = 0, a1 = 0, a2 = 0, a3 = 0;
#pragma unroll
        for (int m = 0; m < 16; m += 2) {
            ulonglong2 x = hq[m];
            ulonglong2 y = hq[m + 1];
            FMA2(a0, wq[2 * m],     x.x);
            FMA2(a1, wq[2 * m + 1], x.y);
            FMA2(a2, wq[2 * m + 2], y.x);
            FMA2(a3, wq[2 * m + 3], y.y);
        }
        ADD2(a0, a2);
        ADD2(a1, a3);
        ADD2(a0, a1);
        float part = __uint_as_float((unsigned)(a0 & 0xFFFFFFFFull)) +
                     __uint_as_float((unsigned)(a0 >> 32));

        // reduce over the 8 segs of each gate group
        unsigned m = 0xFFFFFFFFu;
        part += __shfl_xor_sync(m, part, 1);
        part += __shfl_xor_sync(m, part, 2);
        part += __shfl_xor_sync(m, part, 4);

        if (seg == 0) {
            part += xg_cur;
            if (s + 1 < T) {
                int tn = d ? (t - 1) : (t + 1);
                xg_cur = __ldg(xg + (size_t)tn * G4 + grow);
            }
        }

        float xi  = __shfl_sync(m, part, 0);
        float xf  = __shfl_sync(m, part, 8);
        float xgg = __shfl_sync(m, part, 16);
        float xo  = __shfl_sync(m, part, 24);

        c = sig_f(xf) * c + sig_f(xi) * tanh_f(xgg);
        float hnew = sig_f(xo) * tanh_f(c);
        if (lane == 0) {
            asm volatile("st.volatile.global.f32 [%0], %1;"
                         :: "l"(hout + (size_t)t * HD + row), "f"(hnew));
        }
    }
}

// ---------------- emissions: feats = [hf|hb] @ W_out^T + b_out ----------------
#define FB 16
__global__ void __launch_bounds__(512) k_feats(const float* __restrict__ W_out,
                                               const float* __restrict__ b_out) {
    __shared__ float shp[16 * 68];   // single array: 1024 cols padded to 1088

    int tid = threadIdx.x;
    int tag = tid >> 4, q = tid & 15;

    float4 wr[16];
    const float4* wp = (const float4*)(W_out + (size_t)tag * 1024 + q * 64);
#pragma unroll
    for (int i = 0; i < 16; i++) wr[i] = wp[i];
    float bias = b_out[tag];

    int c  = tid * 2;
    int cs = (c >> 6) * 68 + (c & 63);
    int t0 = blockIdx.x * FB;

    for (int i = 0; i < FB; i++) {
        int t = t0 + i;
        const float* src = (c < 512) ? (g_h[0] + (size_t)t * HD + c)
                                     : (g_h[1] + (size_t)t * HD + (c - 512));
        float2 hv = *(const float2*)src;
        __syncthreads();
        shp[cs]     = hv.x;
        shp[cs + 1] = hv.y;
        __syncthreads();

        const float4* hq = (const float4*)&shp[q * 68];
        float s = 0.f;
#pragma unroll
        for (int k2 = 0; k2 < 16; k2++) {
            float4 h4 = hq[k2];
            float4 w4 = wr[k2];
            s += w4.x * h4.x + w4.y * h4.y + w4.z * h4.z + w4.w * h4.w;
        }
        s += __shfl_xor_sync(0xFFFFFFFFu, s, 1);
        s += __shfl_xor_sync(0xFFFFFFFFu, s, 2);
        s += __shfl_xor_sync(0xFFFFFFFFu, s, 4);
        s += __shfl_xor_sync(0xFFFFFFFFu, s, 8);
        if (q == 0) g_feats[t * TAGS + tag] = s + bias;
    }
}

// ---------------- Viterbi (single warp; tournament-tree exact argmax) --------
// Depth-5 tournament with strict-greater-from-right (left wins ties) = first
// occurrence of the max at every level => global first-max (jnp.argmax).
extern __shared__ unsigned char vit_smem[];
__global__ void k_viterbi(const float* __restrict__ transitions, float* __restrict__ out,
                          int out_size) {
    unsigned char* bp = vit_smem;                    // T*TAGS bytes
    float* fvbuf = (float*)(vit_smem + T * TAGS);    // 2 * TAGS floats (ping-pong)
    int n = threadIdx.x;

    float tr[TAGS];
#pragma unroll
    for (int j = 0; j < TAGS; j++) tr[j] = transitions[n * TAGS + j];

    fvbuf[n] = (n == START) ? 0.f : NEGV;
    __syncwarp();

    float f0 = g_feats[0 * TAGS + n];
    float f1 = g_feats[1 * TAGS + n];

    for (int t = 0; t < T; t++) {
        const float* fv = fvbuf + (t & 1) * TAGS;
        float*       fw = fvbuf + ((t + 1) & 1) * TAGS;

        float m16[16]; int i16[16];
#pragma unroll
        for (int k = 0; k < 16; k++) {
            float vl = fv[2 * k]     + tr[2 * k];
            float vr = fv[2 * k + 1] + tr[2 * k + 1];
            bool g = vr > vl;
            m16[k] = g ? vr : vl;
            i16[k] = g ? 2 * k + 1 : 2 * k;
        }
#pragma unroll
        for (int k = 0; k < 8; k++) {
            bool g = m16[2 * k + 1] > m16[2 * k];
            m16[k] = g ? m16[2 * k + 1] : m16[2 * k];
            i16[k] = g ? i16[2 * k + 1] : i16[2 * k];
        }
#pragma unroll
        for (int k = 0; k < 4; k++) {
            bool g = m16[2 * k + 1] > m16[2 * k];
            m16[k] = g ? m16[2 * k + 1] : m16[2 * k];
            i16[k] = g ? i16[2 * k + 1] : i16[2 * k];
        }
#pragma unroll
        for (int k = 0; k < 2; k++) {
            bool g = m16[2 * k + 1] > m16[2 * k];
            m16[k] = g ? m16[2 * k + 1] : m16[2 * k];
            i16[k] = g ? i16[2 * k + 1] : i16[2 * k];
        }
        bool g = m16[1] > m16[0];
        float best = g ? m16[1] : m16[0];
        int   arg  = g ? i16[1] : i16[0];

        float feat = (t & 1) ? f1 : f0;
        if (t + 2 < T) {
            float nf = g_feats[(t + 2) * TAGS + n];
            if (t & 1) f1 = nf; else f0 = nf;
        }
        bp[t * TAGS + n] = (unsigned char)arg;
        fw[n] = best + feat;
        __syncwarp();
    }

    const float* fvF = fvbuf + (T & 1) * TAGS;
    float term = fvF[n] + transitions[STOP * TAGS + n];
    int best = 0;
    {
        float bb = __shfl_sync(0xFFFFFFFFu, term, 0);
#pragma unroll
        for (int j = 1; j < TAGS; j++) {
            float v = __shfl_sync(0xFFFFFFFFu, term, j);
            if (v > bb) { bb = v; best = j; }
        }
    }
    float score = fvF[best] + transitions[STOP * TAGS + best];

    if (n == 0) {
        if (out_size >= T + 1) {
            out[0] = score;
            int tag = best;
            for (int t = T - 1; t >= 0; t--) {
                out[1 + t] = (float)tag;
                tag = bp[t * TAGS + tag];
            }
        } else if (out_size >= T) {
            int tag = best;
            for (int t = T - 1; t >= 0; t--) {
                out[t] = (float)tag;
                tag = bp[t * TAGS + tag];
            }
        } else {
            out[0] = score;
        }
    }
}

// ---------------- launch ----------------
extern "C" void kernel_launch(void* const* d_in, const int* in_sizes, int n_in,
                              void* d_out, int out_size) {
    const int*   sentence    = (const int*)d_in[0];
    const float* emb         = (const float*)d_in[1];
    const float* w_ih_f      = (const float*)d_in[2];
    const float* w_hh_f      = (const float*)d_in[3];
    const float* b_f         = (const float*)d_in[4];
    const float* w_ih_b      = (const float*)d_in[5];
    const float* w_hh_b      = (const float*)d_in[6];
    const float* b_b         = (const float*)d_in[7];
    const float* W_out       = (const float*)d_in[8];
    const float* b_out       = (const float*)d_in[9];
    const float* transitions = (const float*)d_in[10];
    const float* h0          = (const float*)d_in[11];
    const float* c0          = (const float*)d_in[12];
    float* out = (float*)d_out;

    k_prep<<<T + 2048, 128>>>(sentence, emb);
    k_gemm<<<dim3(16, 16, 2), 256>>>(w_ih_f, b_f, w_ih_b, b_b);
    k_lstm<<<128, 256>>>(w_hh_f, w_hh_b, h0, c0);
    k_feats<<<128, 512>>>(W_out, b_out);

    int vit_smem_bytes = T * TAGS + 2 * TAGS * (int)sizeof(float);
    cudaFuncSetAttribute(k_viterbi, cudaFuncAttributeMaxDynamicSharedMemorySize, vit_smem_bytes);
    k_viterbi<<<1, 32, vit_smem_bytes>>>(transitions, out, out_size);
}

// round 7
// speedup vs baseline: 3.8190x; 3.8190x over previous
#include <cuda_runtime.h>
#include <cstdint>

#define T     2048
#define E     512
#define HD    512
#define G4    2048   /* 4*HD */
#define TAGS  32
#define START 30
#define STOP  31
#define NEGV  (-10000.0f)

#define CANARY 0xFFFFFFFFu

// ---------------- scratch (device globals; no allocation) ----------------
__device__ float g_x[T * E];          // gathered embeddings          4 MB
__device__ float g_xg[2][T * G4];     // precomputed input gates     32 MB
__device__ float g_h[2][T * HD];      // LSTM hidden outputs          8 MB
__device__ float g_feats[T * TAGS];   // emissions                  256 KB

// ---------------- gather + poison fused ----------------
__global__ void k_prep(const int* __restrict__ sent, const float* __restrict__ emb) {
    int blk = blockIdx.x;
    if (blk < T) {
        const float4* src = (const float4*)(emb + (size_t)sent[blk] * E);
        ((float4*)(g_x + (size_t)blk * E))[threadIdx.x] = src[threadIdx.x];
    } else {
        int cb = blk - T;
        unsigned* dst = (unsigned*)g_h + (size_t)cb * 1024 + threadIdx.x * 8;
        uint4 v = {CANARY, CANARY, CANARY, CANARY};
        *(uint4*)(dst)     = v;
        *(uint4*)(dst + 4) = v;
    }
}

// ---------------- packed f32x2 helpers ----------------
#define FMA2(acc, a, b) asm("fma.rn.f32x2 %0, %1, %2, %0;" : "+l"(acc) : "l"(a), "l"(b))
#define ADD2(acc, b)    asm("add.rn.f32x2 %0, %0, %1;" : "+l"(acc) : "l"(b))
#define PACK2(out, lo, hi) asm("mov.b64 %0, {%1, %2};" : "=l"(out) : "f"(lo), "f"(hi))

// ---------------- input GEMM: g_xg[d] = g_x @ W_ih[d]^T + b[d] (FFMA2) -------
#define BM 128
#define BN 128
#define BK 16
__global__ void __launch_bounds__(256) k_gemm(const float* __restrict__ w_ih_f,
                                              const float* __restrict__ b_f,
                                              const float* __restrict__ w_ih_b,
                                              const float* __restrict__ b_b) {
    int d = blockIdx.z;
    const float* W    = d ? w_ih_b : w_ih_f;
    const float* bias = d ? b_b    : b_f;

    __shared__ float As[BK][BM];
    __shared__ float Bs[BK][BN];

    int tid = threadIdx.x;
    int tx = tid & 15, ty = tid >> 4;
    int t0 = blockIdx.y * BM, r0 = blockIdx.x * BN;

    unsigned long long acc2[8][4];
#pragma unroll
    for (int i = 0; i < 8; i++)
#pragma unroll
        for (int j = 0; j < 4; j++) acc2[i][j] = 0ull;

    int lm = tid >> 2;            // 0..63
    int lk = (tid & 3) * 4;       // 0,4,8,12

    for (int k0 = 0; k0 < E; k0 += BK) {
#pragma unroll
        for (int rep = 0; rep < 2; rep++) {
            float4 v = *(const float4*)(g_x + (size_t)(t0 + lm + rep * 64) * E + k0 + lk);
            As[lk + 0][lm + rep * 64] = v.x;
            As[lk + 1][lm + rep * 64] = v.y;
            As[lk + 2][lm + rep * 64] = v.z;
            As[lk + 3][lm + rep * 64] = v.w;
            float4 w = *(const float4*)(W + (size_t)(r0 + lm + rep * 64) * E + k0 + lk);
            Bs[lk + 0][lm + rep * 64] = w.x;
            Bs[lk + 1][lm + rep * 64] = w.y;
            Bs[lk + 2][lm + rep * 64] = w.z;
            Bs[lk + 3][lm + rep * 64] = w.w;
        }
        __syncthreads();
#pragma unroll
        for (int k = 0; k < BK; k++) {
            float a[8];
            *(float4*)(a)     = *(const float4*)&As[k][ty * 8];
            *(float4*)(a + 4) = *(const float4*)&As[k][ty * 8 + 4];
            ulonglong2 bl = *(const ulonglong2*)&Bs[k][tx * 8];
            ulonglong2 bh = *(const ulonglong2*)&Bs[k][tx * 8 + 4];
            unsigned long long bq[4] = {bl.x, bl.y, bh.x, bh.y};
#pragma unroll
            for (int i = 0; i < 8; i++) {
                unsigned long long ad;
                PACK2(ad, a[i], a[i]);
                FMA2(acc2[i][0], ad, bq[0]);
                FMA2(acc2[i][1], ad, bq[1]);
                FMA2(acc2[i][2], ad, bq[2]);
                FMA2(acc2[i][3], ad, bq[3]);
            }
        }
        __syncthreads();
    }

    float* out = g_xg[d];
#pragma unroll
    for (int i = 0; i < 8; i++) {
        int t = t0 + ty * 8 + i;
#pragma unroll
        for (int jp = 0; jp < 4; jp += 2) {
            int r = r0 + tx * 8 + jp * 2;
            float4 v;
            v.x = __uint_as_float((unsigned)(acc2[i][jp]     & 0xFFFFFFFFull)) + bias[r + 0];
            v.y = __uint_as_float((unsigned)(acc2[i][jp]     >> 32))           + bias[r + 1];
            v.z = __uint_as_float((unsigned)(acc2[i][jp + 1] & 0xFFFFFFFFull)) + bias[r + 2];
            v.w = __uint_as_float((unsigned)(acc2[i][jp + 1] >> 32))           + bias[r + 3];
            *(float4*)(out + (size_t)t * G4 + r) = v;
        }
    }
}

// ---------------- persistent bidirectional LSTM recurrence ----------------
// R2 structure (measured best): 128 CTAs x 288 threads.
// Warps 0-7 (producers): poll own 64-col segment of h_prev (one v2 volatile
// load/thread), stage to smem, packed-f32x2 dot with register-resident W_hh,
// STS partial, bar.arrive (never block).
// Warp 8 (reducer): bar.sync, sum partials, fast-div activations on 8
// predicated lanes ONLY (MUFU is quarter-rate: never replicate transcendental
// math across lanes), publish h (data-as-flag into canary-poisoned g_h).
__device__ __forceinline__ float sig_f(float x) {
    return __fdividef(1.f, 1.f + __expf(-x));
}
__device__ __forceinline__ float tanh_f(float x) {
    return 1.f - __fdividef(2.f, __expf(2.f * x) + 1.f);
}

__global__ void __launch_bounds__(288, 1) k_lstm(const float* __restrict__ w_hh_f,
                                                 const float* __restrict__ w_hh_b,
                                                 const float* __restrict__ h0,
                                                 const float* __restrict__ c0) {
    int cta = blockIdx.x;
    int d = cta >> 6;
    int b = cta & 63;
    const float* Whh = d ? w_hh_b : w_hh_f;

    int tid  = threadIdx.x;
    int wid  = tid >> 5;
    int lane = tid & 31;

    __shared__ float sh_h[HD];
    __shared__ float sh_part[8 * 32];

    float* hout = g_h[d];

    if (wid < 8) {
        // ---------------- producer warp ----------------
        int seg  = wid;
        int gate = lane >> 3, jj = lane & 7;
        int grow = gate * HD + b * 8 + jj;

        unsigned long long wq[32];
        {
            const ulonglong2* wr = (const ulonglong2*)(Whh + (size_t)grow * HD + seg * 64);
#pragma unroll
            for (int m = 0; m < 16; m++) {
                ulonglong2 v = wr[m];
                wq[2 * m] = v.x; wq[2 * m + 1] = v.y;
            }
        }

        for (int s = 0; s < T; s++) {
            int t = d ? (T - 1 - s) : s;
            float2 hv;
            if (s == 0) {
                hv = *(const float2*)(h0 + d * HD + seg * 64 + lane * 2);
            } else {
                int tp = d ? (t + 1) : (t - 1);
                const float* hp = hout + (size_t)tp * HD + seg * 64 + lane * 2;
                unsigned a, bb;
                do {
                    asm volatile("ld.volatile.global.v2.u32 {%0, %1}, [%2];"
                                 : "=r"(a), "=r"(bb) : "l"(hp));
                } while (a == CANARY || bb == CANARY);
                hv.x = __uint_as_float(a);
                hv.y = __uint_as_float(bb);
            }
            sh_h[seg * 64 + lane * 2]     = hv.x;
            sh_h[seg * 64 + lane * 2 + 1] = hv.y;
            __syncwarp();

            unsigned long long a0 = 0, a1 = 0, a2 = 0, a3 = 0;
            const ulonglong2* hq = (const ulonglong2*)(sh_h + seg * 64);
#pragma unroll
            for (int m = 0; m < 16; m += 2) {
                ulonglong2 x = hq[m];
                ulonglong2 y = hq[m + 1];
                FMA2(a0, wq[2 * m],     x.x);
                FMA2(a1, wq[2 * m + 1], x.y);
                FMA2(a2, wq[2 * m + 2], y.x);
                FMA2(a3, wq[2 * m + 3], y.y);
            }
            ADD2(a0, a2);
            ADD2(a1, a3);
            ADD2(a0, a1);
            float part = __uint_as_float((unsigned)(a0 & 0xFFFFFFFFull)) +
                         __uint_as_float((unsigned)(a0 >> 32));
            sh_part[seg * 32 + lane] = part;
            asm volatile("bar.arrive 1, 288;");
        }
    } else {
        // ---------------- reducer warp ----------------
        int gate = lane >> 3, jj = lane & 7;
        int grow = gate * HD + b * 8 + jj;
        const float* xg = g_xg[d];

        float c = 0.f;
        if (lane < 8) c = c0[d * HD + b * 8 + lane];

        int t0i = d ? (T - 1) : 0;
        float xg_cur = __ldg(xg + (size_t)t0i * G4 + grow);

        for (int s = 0; s < T; s++) {
            int t = d ? (T - 1 - s) : s;
            asm volatile("bar.sync 1, 288;");

            float xg_use = xg_cur;
            if (s + 1 < T) {
                int tn = d ? (t - 1) : (t + 1);
                xg_cur = __ldg(xg + (size_t)tn * G4 + grow);
            }

            float t0a = sh_part[0 * 32 + lane] + sh_part[1 * 32 + lane];
            float t1a = sh_part[2 * 32 + lane] + sh_part[3 * 32 + lane];
            float t2a = sh_part[4 * 32 + lane] + sh_part[5 * 32 + lane];
            float t3a = sh_part[6 * 32 + lane] + sh_part[7 * 32 + lane];
            float tot = xg_use + ((t0a + t1a) + (t2a + t3a));

            unsigned m = 0xFFFFFFFFu;
            float xi  = __shfl_sync(m, tot, (lane & 7));
            float xf  = __shfl_sync(m, tot, 8 + (lane & 7));
            float xgg = __shfl_sync(m, tot, 16 + (lane & 7));
            float xo  = __shfl_sync(m, tot, 24 + (lane & 7));
            if (lane < 8) {
                c = sig_f(xf) * c + sig_f(xi) * tanh_f(xgg);
                float hnew = sig_f(xo) * tanh_f(c);
                asm volatile("st.volatile.global.f32 [%0], %1;"
                             :: "l"(hout + (size_t)t * HD + b * 8 + lane), "f"(hnew));
            }
        }
    }
}

// ---------------- emissions: feats = [hf|hb] @ W_out^T + b_out ----------------
#define FB 16
__global__ void __launch_bounds__(512) k_feats(const float* __restrict__ W_out,
                                               const float* __restrict__ b_out) {
    __shared__ float shp[16 * 68];   // single array: 1024 cols padded to 1088

    int tid = threadIdx.x;
    int tag = tid >> 4, q = tid & 15;

    float4 wr[16];
    const float4* wp = (const float4*)(W_out + (size_t)tag * 1024 + q * 64);
#pragma unroll
    for (int i = 0; i < 16; i++) wr[i] = wp[i];
    float bias = b_out[tag];

    int c  = tid * 2;
    int cs = (c >> 6) * 68 + (c & 63);
    int t0 = blockIdx.x * FB;

    for (int i = 0; i < FB; i++) {
        int t = t0 + i;
        const float* src = (c < 512) ? (g_h[0] + (size_t)t * HD + c)
                                     : (g_h[1] + (size_t)t * HD + (c - 512));
        float2 hv = *(const float2*)src;
        __syncthreads();
        shp[cs]     = hv.x;
        shp[cs + 1] = hv.y;
        __syncthreads();

        const float4* hq = (const float4*)&shp[q * 68];
        float s = 0.f;
#pragma unroll
        for (int k2 = 0; k2 < 16; k2++) {
            float4 h4 = hq[k2];
            float4 w4 = wr[k2];
            s += w4.x * h4.x + w4.y * h4.y + w4.z * h4.z + w4.w * h4.w;
        }
        s += __shfl_xor_sync(0xFFFFFFFFu, s, 1);
        s += __shfl_xor_sync(0xFFFFFFFFu, s, 2);
        s += __shfl_xor_sync(0xFFFFFFFFu, s, 4);
        s += __shfl_xor_sync(0xFFFFFFFFu, s, 8);
        if (q == 0) g_feats[t * TAGS + tag] = s + bias;
    }
}

// ---------------- Viterbi (single warp; tournament-tree exact argmax) --------
// Depth-5 tournament, left wins ties at every level => global first-max
// (jnp.argmax semantics). Validated rel_err = 0.0 in R6.
extern __shared__ unsigned char vit_smem[];
__global__ void k_viterbi(const float* __restrict__ transitions, float* __restrict__ out,
                          int out_size) {
    unsigned char* bp = vit_smem;                    // T*TAGS bytes
    float* fvbuf = (float*)(vit_smem + T * TAGS);    // 2 * TAGS floats (ping-pong)
    int n = threadIdx.x;

    float tr[TAGS];
#pragma unroll
    for (int j = 0; j < TAGS; j++) tr[j] = transitions[n * TAGS + j];

    fvbuf[n] = (n == START) ? 0.f : NEGV;
    __syncwarp();

    float f0 = g_feats[0 * TAGS + n];
    float f1 = g_feats[1 * TAGS + n];

    for (int t = 0; t < T; t++) {
        const float* fv = fvbuf + (t & 1) * TAGS;
        float*       fw = fvbuf + ((t + 1) & 1) * TAGS;

        float m16[16]; int i16[16];
#pragma unroll
        for (int k = 0; k < 16; k++) {
            float vl = fv[2 * k]     + tr[2 * k];
            float vr = fv[2 * k + 1] + tr[2 * k + 1];
            bool g = vr > vl;
            m16[k] = g ? vr : vl;
            i16[k] = g ? 2 * k + 1 : 2 * k;
        }
#pragma unroll
        for (int k = 0; k < 8; k++) {
            bool g = m16[2 * k + 1] > m16[2 * k];
            m16[k] = g ? m16[2 * k + 1] : m16[2 * k];
            i16[k] = g ? i16[2 * k + 1] : i16[2 * k];
        }
#pragma unroll
        for (int k = 0; k < 4; k++) {
            bool g = m16[2 * k + 1] > m16[2 * k];
            m16[k] = g ? m16[2 * k + 1] : m16[2 * k];
            i16[k] = g ? i16[2 * k + 1] : i16[2 * k];
        }
#pragma unroll
        for (int k = 0; k < 2; k++) {
            bool g = m16[2 * k + 1] > m16[2 * k];
            m16[k] = g ? m16[2 * k + 1] : m16[2 * k];
            i16[k] = g ? i16[2 * k + 1] : i16[2 * k];
        }
        bool g = m16[1] > m16[0];
        float best = g ? m16[1] : m16[0];
        int   arg  = g ? i16[1] : i16[0];

        float feat = (t & 1) ? f1 : f0;
        if (t + 2 < T) {
            float nf = g_feats[(t + 2) * TAGS + n];
            if (t & 1) f1 = nf; else f0 = nf;
        }
        bp[t * TAGS + n] = (unsigned char)arg;
        fw[n] = best + feat;
        __syncwarp();
    }

    const float* fvF = fvbuf + (T & 1) * TAGS;
    float term = fvF[n] + transitions[STOP * TAGS + n];
    int best = 0;
    {
        float bb = __shfl_sync(0xFFFFFFFFu, term, 0);
#pragma unroll
        for (int j = 1; j < TAGS; j++) {
            float v = __shfl_sync(0xFFFFFFFFu, term, j);
            if (v > bb) { bb = v; best = j; }
        }
    }
    float score = fvF[best] + transitions[STOP * TAGS + best];

    if (n == 0) {
        if (out_size >= T + 1) {
            out[0] = score;
            int tag = best;
            for (int t = T - 1; t >= 0; t--) {
                out[1 + t] = (float)tag;
                tag = bp[t * TAGS + tag];
            }
        } else if (out_size >= T) {
            int tag = best;
            for (int t = T - 1; t >= 0; t--) {
                out[t] = (float)tag;
                tag = bp[t * TAGS + tag];
            }
        } else {
            out[0] = score;
        }
    }
}

// ---------------- launch ----------------
extern "C" void kernel_launch(void* const* d_in, const int* in_sizes, int n_in,
                              void* d_out, int out_size) {
    const int*   sentence    = (const int*)d_in[0];
    const float* emb         = (const float*)d_in[1];
    const float* w_ih_f      = (const float*)d_in[2];
    const float* w_hh_f      = (const float*)d_in[3];
    const float* b_f         = (const float*)d_in[4];
    const float* w_ih_b      = (const float*)d_in[5];
    const float* w_hh_b      = (const float*)d_in[6];
    const float* b_b         = (const float*)d_in[7];
    const float* W_out       = (const float*)d_in[8];
    const float* b_out       = (const float*)d_in[9];
    const float* transitions = (const float*)d_in[10];
    const float* h0          = (const float*)d_in[11];
    const float* c0          = (const float*)d_in[12];
    float* out = (float*)d_out;

    k_prep<<<T + 2048, 128>>>(sentence, emb);
    k_gemm<<<dim3(16, 16, 2), 256>>>(w_ih_f, b_f, w_ih_b, b_b);
    k_lstm<<<128, 288>>>(w_hh_f, w_hh_b, h0, c0);
    k_feats<<<128, 512>>>(W_out, b_out);

    int vit_smem_bytes = T * TAGS + 2 * TAGS * (int)sizeof(float);
    cudaFuncSetAttribute(k_viterbi, cudaFuncAttributeMaxDynamicSharedMemorySize, vit_smem_bytes);
    k_viterbi<<<1, 32, vit_smem_bytes>>>(transitions, out, out_size);
}